// round 1
// baseline (speedup 1.0000x reference)
#include <cuda_runtime.h>

// LSTM: B=4096, T=256, F=18, H=64, gates i,f,g,o (4H=256), classifier O=15.
// One CTA = 32 batch rows for the full sequence. 128 CTAs x 128 threads.
// Recurrent + input matmul fused in one 82-long k loop using packed f32x2 FMA.

#define B_TOT 4096
#define T_LEN 256
#define F_IN  18
#define H_DIM 64
#define G_DIM 256
#define O_DIM 15
#define KK    (H_DIM + F_IN)   // 82
#define ROWS  32
#define NTHR  128
#define NCTA  (B_TOT / ROWS)   // 128

typedef unsigned long long u64;

// ---- shared memory layout (bytes) ----
#define SM_WT    0                         // float Wt[82][256]      = 83968
#define SM_ACT   83968                     // u64   act[32][82]      = 20992 (float2{v,v})
#define SM_BS    104960                    // float bs[256]          = 1024
#define SM_WCLS  105984                    // float wcls[15*64]      = 3840
#define SM_BCLS  109824                    // float bcls[16]         = 64
#define SM_TOTAL 109888

__device__ __forceinline__ u64 pack2(float x, float y) {
    u64 r; asm("mov.b64 %0, {%1, %2};" : "=l"(r) : "f"(x), "f"(y)); return r;
}
__device__ __forceinline__ void unpack2(u64 v, float& x, float& y) {
    asm("mov.b64 {%0, %1}, %2;" : "=f"(x), "=f"(y) : "l"(v));
}
__device__ __forceinline__ void fma2(u64& d, u64 a, u64 b) {
    asm("fma.rn.f32x2 %0, %1, %2, %3;" : "=l"(d) : "l"(a), "l"(b), "l"(d));
}

// accurate fast sigmoid/tanh (MUFU.EX2 + MUFU.RCP, ~1e-6 rel err, inf-safe)
__device__ __forceinline__ float sig_(float x) {
    float e = __expf(-x);
    return __fdividef(1.0f, 1.0f + e);
}
__device__ __forceinline__ float tanh_(float x) {
    float e = __expf(2.0f * x);           // x<<0: e->0 => -1 ; x>>0: e->inf => 1
    return 1.0f - __fdividef(2.0f, e + 1.0f);
}

__global__ void __launch_bounds__(NTHR, 1) lstm_kernel(
    const float* __restrict__ X,      // [B,T,F]
    const float* __restrict__ W_ih,   // [4H,F]
    const float* __restrict__ W_hh,   // [4H,H]
    const float* __restrict__ b_ih,   // [4H]
    const float* __restrict__ b_hh,   // [4H]
    const float* __restrict__ W_cls,  // [O,H]
    const float* __restrict__ b_cls,  // [O]
    float* __restrict__ out)          // [B,O]
{
    extern __shared__ char sm[];
    float* Wt   = (float*)(sm + SM_WT);     // Wt[k][g]: k<64 -> W_hh[g][k]; k=64+f -> W_ih[g][f]
    u64*   actu = (u64*)  (sm + SM_ACT);    // act[b][k] = float2{v,v}; k<64: h, k>=64: x(t)
    float* actf = (float*)(sm + SM_ACT);
    float* bs   = (float*)(sm + SM_BS);
    float* wcls = (float*)(sm + SM_WCLS);
    float* bcl  = (float*)(sm + SM_BCLS);

    const int tid  = threadIdx.x;
    const int tg   = tid & 15;   // gate-column group: owns j in {2tg,2tg+1,2tg+32,2tg+33}
    const int tr   = tid >> 4;   // row group: rows tr*4 .. tr*4+3
    const int row0 = blockIdx.x * ROWS;

    // ---- one-time setup: stage transposed weights / biases, zero h ----
    for (int i = tid; i < H_DIM * G_DIM; i += NTHR) {
        int k = i >> 8, g = i & 255;
        Wt[k * G_DIM + g] = W_hh[g * H_DIM + k];
    }
    for (int i = tid; i < F_IN * G_DIM; i += NTHR) {
        int f = i >> 8, g = i & 255;
        Wt[(H_DIM + f) * G_DIM + g] = W_ih[g * F_IN + f];
    }
    for (int g = tid; g < G_DIM; g += NTHR) bs[g] = b_ih[g] + b_hh[g];
    for (int i = tid; i < O_DIM * H_DIM; i += NTHR) wcls[i] = W_cls[i];
    if (tid < O_DIM) bcl[tid] = b_cls[tid];
    for (int i = tid; i < ROWS * H_DIM; i += NTHR) {
        int b = i >> 6, j = i & 63;
        actu[b * KK + j] = 0ull;
    }
    __syncthreads();

    // gate-pair biases (g0 = 64q + 32p + 2tg) kept in registers
    u64 biasv[4][2];
#pragma unroll
    for (int q = 0; q < 4; q++)
#pragma unroll
        for (int p = 0; p < 2; p++)
            biasv[q][p] = ((const u64*)bs)[q * 32 + p * 16 + tg];

    // X prefetch assignment: element e = tid + 128*m of the 32x18 step tile
    int pb[5], pf[5]; bool pv[5];
#pragma unroll
    for (int m = 0; m < 5; m++) {
        int e = tid + NTHR * m;
        pv[m] = (e < ROWS * F_IN);
        int b = e / F_IN;
        pb[m] = b;
        pf[m] = e - b * F_IN;
    }
    const float* Xbase = X + (long long)row0 * T_LEN * F_IN;
    float xp[5];
#pragma unroll
    for (int m = 0; m < 5; m++)
        xp[m] = pv[m] ? Xbase[(long long)pb[m] * (T_LEN * F_IN) + pf[m]] : 0.0f;

    float hreg[4][4];   // [r][2p+half] ; h_{-1} = 0
    float creg[4][4];
#pragma unroll
    for (int r = 0; r < 4; r++)
#pragma unroll
        for (int c = 0; c < 4; c++) { hreg[r][c] = 0.0f; creg[r][c] = 0.0f; }

    // ================= time loop =================
    for (int t = 0; t < T_LEN; ++t) {
        __syncthreads();  // previous k-loop readers done

        // publish x_t (duplicated) and h_{t-1} (duplicated)
#pragma unroll
        for (int m = 0; m < 5; m++)
            if (pv[m]) actu[pb[m] * KK + H_DIM + pf[m]] = pack2(xp[m], xp[m]);
#pragma unroll
        for (int r = 0; r < 4; r++) {
            int b = tr * 4 + r;
#pragma unroll
            for (int p = 0; p < 2; p++) {
                int j = p * 32 + 2 * tg;
                actu[b * KK + j]     = pack2(hreg[r][2 * p],     hreg[r][2 * p]);
                actu[b * KK + j + 1] = pack2(hreg[r][2 * p + 1], hreg[r][2 * p + 1]);
            }
        }
        __syncthreads();

        // prefetch x_{t+1} under the k-loop
        if (t + 1 < T_LEN) {
#pragma unroll
            for (int m = 0; m < 5; m++)
                if (pv[m])
                    xp[m] = Xbase[(long long)pb[m] * (T_LEN * F_IN) + (t + 1) * F_IN + pf[m]];
        }

        // gates = bias + [h | x] @ Wt   (82-long k loop, f32x2 packed over gate pairs)
        u64 acc[4][4][2];
#pragma unroll
        for (int r = 0; r < 4; r++)
#pragma unroll
            for (int q = 0; q < 4; q++)
#pragma unroll
                for (int p = 0; p < 2; p++) acc[r][q][p] = biasv[q][p];

        const u64* wt2 = (const u64*)Wt;  // row k = 128 u64
        const int ab = tr * 4 * KK;
#pragma unroll 2
        for (int k = 0; k < KK; k++) {
            u64 a0 = actu[ab + k];
            u64 a1 = actu[ab + KK + k];
            u64 a2 = actu[ab + 2 * KK + k];
            u64 a3 = actu[ab + 3 * KK + k];
            const u64* wrow = wt2 + k * 128 + tg;
#pragma unroll
            for (int q = 0; q < 4; q++)
#pragma unroll
                for (int p = 0; p < 2; p++) {
                    u64 w = wrow[q * 32 + p * 16];
                    fma2(acc[0][q][p], a0, w);
                    fma2(acc[1][q][p], a1, w);
                    fma2(acc[2][q][p], a2, w);
                    fma2(acc[3][q][p], a3, w);
                }
        }

        // elementwise LSTM cell update (this thread owns full i/f/g/o for its j's)
#pragma unroll
        for (int r = 0; r < 4; r++) {
#pragma unroll
            for (int p = 0; p < 2; p++) {
                float i0, i1, f0, f1, g0, g1, o0, o1;
                unpack2(acc[r][0][p], i0, i1);
                unpack2(acc[r][1][p], f0, f1);
                unpack2(acc[r][2][p], g0, g1);
                unpack2(acc[r][3][p], o0, o1);
                float c0 = creg[r][2 * p], c1 = creg[r][2 * p + 1];
                c0 = sig_(f0) * c0 + sig_(i0) * tanh_(g0);
                c1 = sig_(f1) * c1 + sig_(i1) * tanh_(g1);
                creg[r][2 * p]     = c0;
                creg[r][2 * p + 1] = c1;
                hreg[r][2 * p]     = sig_(o0) * tanh_(c0);
                hreg[r][2 * p + 1] = sig_(o1) * tanh_(c1);
            }
        }
    }

    // ---- classifier head on final h ----
    __syncthreads();
#pragma unroll
    for (int r = 0; r < 4; r++) {
        int b = tr * 4 + r;
#pragma unroll
        for (int p = 0; p < 2; p++) {
            int j = p * 32 + 2 * tg;
            actu[b * KK + j]     = pack2(hreg[r][2 * p],     hreg[r][2 * p]);
            actu[b * KK + j + 1] = pack2(hreg[r][2 * p + 1], hreg[r][2 * p + 1]);
        }
    }
    __syncthreads();

    for (int e = tid; e < ROWS * O_DIM; e += NTHR) {
        int b = e / O_DIM, o = e - b * O_DIM;
        float s = bcl[o];
#pragma unroll
        for (int j = 0; j < H_DIM; j++)
            s += actf[(b * KK + j) * 2] * wcls[o * H_DIM + j];
        out[(long long)(row0 + b) * O_DIM + o] = s;
    }
}

extern "C" void kernel_launch(void* const* d_in, const int* in_sizes, int n_in,
                              void* d_out, int out_size)
{
    const float* X     = (const float*)d_in[0];
    const float* W_ih  = (const float*)d_in[1];
    const float* W_hh  = (const float*)d_in[2];
    const float* b_ih  = (const float*)d_in[3];
    const float* b_hh  = (const float*)d_in[4];
    const float* W_cls = (const float*)d_in[5];
    const float* b_cls = (const float*)d_in[6];

    cudaFuncSetAttribute(lstm_kernel,
                         cudaFuncAttributeMaxDynamicSharedMemorySize, SM_TOTAL);
    lstm_kernel<<<NCTA, NTHR, SM_TOTAL>>>(X, W_ih, W_hh, b_ih, b_hh,
                                          W_cls, b_cls, (float*)d_out);
}